// round 1
// baseline (speedup 1.0000x reference)
#include <cuda_runtime.h>
#include <cuda_bf16.h>

// ---------------------------------------------------------------------------
// LoongSpikeKernel: K[ch,h,l] = 2*Re( sum_n C_disc[h,n] * exp(dtA[h,n]*l) )
// H=512, M*NST=64 states/h, L=2048, CH=1.
//
// Plan:
//   Kernel 1 (pre):  per (h, j) compute dtA (complex), C2 = 2*C_disc (complex),
//                    and r64 = exp(64*dtA) packed as (rr, _, -ri, ri).
//   Kernel 2 (main): one block per h (64 threads). Thread t owns l = t + 64k.
//                    Seeds z_n = C2_n * exp(dtA_n * t) exactly, then per k:
//                    acc += z_n (f32x2), z_n *= r64 (f32x2 complex mult).
//                    Store acc.lo -> out[h*L + t + 64k]  (fully coalesced).
// ---------------------------------------------------------------------------

#define NS 64  // states per h (M*NST)

// Scratch (device globals; allocation-free rule)
__device__ float2 g_dtA[512 * NS];
__device__ float2 g_C2 [512 * NS];
__device__ float4 g_R64[512 * NS];

__device__ __forceinline__ void sincos_dr(float x, float* s, float* c) {
    // accurate sin/cos of an f32 value: double Cody-Waite reduction + fast sincos
    double pd = (double)x;
    double k  = rint(pd * 0.15915494309189535);      // x / (2*pi)
    float red = (float)__fma_rn(k, -6.283185307179586, pd);
    __sincosf(red, s, c);
}

__device__ __forceinline__ unsigned long long pack2(float lo, float hi) {
    unsigned long long r;
    asm("mov.b64 %0, {%1, %2};" : "=l"(r)
        : "r"(__float_as_uint(lo)), "r"(__float_as_uint(hi)));
    return r;
}

// acc += z; z = z * r   where r = (rr + i*ri), z packed (re=lo, im=hi)
// nri = __float_as_uint(-ri), pri = __float_as_uint(ri), rr splat.
__device__ __forceinline__ void cstep(unsigned long long& z, unsigned long long& acc,
                                      unsigned rr, unsigned nri, unsigned pri) {
    asm("{\n\t"
        ".reg .b32 zl, zh;\n\t"
        ".reg .b64 rrp, rip, sw, u;\n\t"
        "mov.b64 rrp, {%2, %2};\n\t"
        "mov.b64 rip, {%3, %4};\n\t"
        "add.rn.f32x2 %1, %1, %0;\n\t"
        "mov.b64 {zl, zh}, %0;\n\t"
        "mov.b64 sw, {zh, zl};\n\t"
        "mul.rn.f32x2 u, sw, rip;\n\t"
        "fma.rn.f32x2 %0, %0, rrp, u;\n\t"
        "}\n"
        : "+l"(z), "+l"(acc)
        : "r"(rr), "r"(nri), "r"(pri));
}

// ---------------------------------------------------------------------------
__global__ void loong_pre(const float* __restrict__ C_real,
                          const float* __restrict__ log_dt,
                          const float* __restrict__ log_A_real,
                          const float* __restrict__ A_imag,
                          const float* __restrict__ omega_logit,
                          const float* __restrict__ eta_logit,
                          int H, int NST, int M) {
    const float OMIN = 1e-6f, OMAX = 100.0f, EMIN = 1e-6f, EMAX = 10.0f;
    int idx = blockIdx.x * blockDim.x + threadIdx.x;
    int total = H * M * NST;
    if (idx >= total) return;
    int h = idx / (M * NST);
    int j = idx - h * (M * NST);
    int m = j / NST;
    int n = j - m * NST;

    float dt    = expf(log_dt[h]);
    float omega = OMIN + (OMAX - OMIN) / (1.f + expf(-omega_logit[m]));
    float eta   = EMIN + (EMAX - EMIN) / (1.f + expf(-eta_logit[m]));
    float Are   = -expf(log_A_real[h * NST + n]);
    float Aim   = A_imag[h * NST + n];
    float Afr   = -omega + eta * Are;
    float Afi   = eta * Aim;
    float Cr    = eta * C_real[(h * NST + n) * 2 + 0];   // CH = 1
    float Ci    = eta * C_real[(h * NST + n) * 2 + 1];
    float dtAr  = Afr * dt;
    float dtAi  = Afi * dt;

    // exp(dtA) - 1
    float er = expf(dtAr);
    float s1, c1; sincos_dr(dtAi, &s1, &c1);
    float nr = er * c1 - 1.f;
    float ni = er * s1;
    // / (A_frac + 1e-8)
    float dr  = Afr + 1e-8f, di = Afi;
    float inv = 1.f / (dr * dr + di * di);
    float qr  = (nr * dr + ni * di) * inv;
    float qi  = (ni * dr - nr * di) * inv;
    float Cdr = Cr * qr - Ci * qi;
    float Cdi = Cr * qi + Ci * qr;
    if (sqrtf(Afr * Afr + Afi * Afi) < 1e-6f) { Cdr = Cr * dt; Cdi = Ci * dt; }

    g_dtA[idx] = make_float2(dtAr, dtAi);
    g_C2 [idx] = make_float2(2.f * Cdr, 2.f * Cdi);

    // r64 = exp(64 * dtA)   (x64 is exact in fp32)
    float e64 = expf(64.f * dtAr);
    float s64, c64; sincos_dr(64.f * dtAi, &s64, &c64);
    float rr = e64 * c64, ri = e64 * s64;
    g_R64[idx] = make_float4(rr, 0.f, -ri, ri);
}

// ---------------------------------------------------------------------------
__global__ __launch_bounds__(64) void loong_main(float* __restrict__ out, int L) {
    int h = blockIdx.x;
    int t = threadIdx.x;                  // 0..63, owns l = t + 64k

    __shared__ float4 sQ[NS];
    __shared__ float2 sA[NS];
    __shared__ float2 sC[NS];
    int base = h * NS;
    sQ[t] = g_R64[base + t];
    sA[t] = g_dtA[base + t];
    sC[t] = g_C2 [base + t];
    __syncthreads();

    // Seed: z_n = C2_n * exp(dtA_n * t)
    unsigned long long z[NS];
    float tf = (float)t;
#pragma unroll
    for (int n = 0; n < NS; n++) {
        float2 a = sA[n];
        float2 c = sC[n];
        float er = __expf(a.x * tf);
        float ph = a.y * tf;              // same fl product as reference
        float s, co; sincos_dr(ph, &s, &co);
        float zr = er * co, zi = er * s;
        float wr = c.x * zr - c.y * zi;
        float wi = c.x * zi + c.y * zr;
        z[n] = pack2(wr, wi);
    }

    float* outp = out + (long long)h * L + t;
    int iters = (L + 63) >> 6;
#pragma unroll 1
    for (int k = 0; k < iters; k++) {
        unsigned long long acc = 0ull;
#pragma unroll
        for (int n = 0; n < NS; n++) {
            float4 q = sQ[n];             // LDS.128 broadcast: (rr, _, -ri, ri)
            cstep(z[n], acc,
                  __float_as_uint(q.x), __float_as_uint(q.z), __float_as_uint(q.w));
        }
        int l = t + (k << 6);
        if (l < L) outp[(long long)(k << 6)] = __uint_as_float((unsigned)acc);
    }
}

// ---------------------------------------------------------------------------
extern "C" void kernel_launch(void* const* d_in, const int* in_sizes, int n_in,
                              void* d_out, int out_size) {
    const float* C_real      = (const float*)d_in[0];
    const float* log_dt      = (const float*)d_in[1];
    const float* log_A_real  = (const float*)d_in[2];
    const float* A_imag      = (const float*)d_in[3];
    const float* omega_logit = (const float*)d_in[4];
    const float* eta_logit   = (const float*)d_in[5];

    int H   = in_sizes[1];               // 512
    int NST = in_sizes[2] / H;           // 32
    int M   = in_sizes[4];               // 2
    int L   = out_size / H;              // 2048 (CH = 1)

    int total = H * M * NST;
    loong_pre<<<(total + 127) / 128, 128>>>(C_real, log_dt, log_A_real, A_imag,
                                            omega_logit, eta_logit, H, NST, M);
    loong_main<<<H, 64>>>((float*)d_out, L);
}

// round 2
// speedup vs baseline: 11.3449x; 11.3449x over previous
#include <cuda_runtime.h>
#include <cuda_bf16.h>

// ---------------------------------------------------------------------------
// LoongSpikeKernel: K[ch,h,l] = 2*Re( sum_n C_disc[h,n] * exp(dtA[h,n]*l) )
// H=512, NS=64 states/h, L=2048, CH=1.
//
// R2 design: 256 threads/block, 1 block per h.
//   tid = g*64 + t : g = state-group (4 groups x 16 states), t = l-lane.
//   Thread seeds z_i = C2 * exp(dtA * t) for its 16 states, then per k-iter
//   advances z_i *= r64 (packed f32x2 complex mult) and accumulates.
//   All state + rotation constants live in REGISTERS (R1 failure: z[64]
//   demoted to local memory -> 449GB/s of spill traffic).
//   Per-k real partials go to smem; one sync; coalesced 4-way-sum epilogue.
// ---------------------------------------------------------------------------

#define NS 64   // states per h (M*NST)
#define GS 16   // states per thread
#define KCHUNK 32

// Scratch (device globals; allocation-free rule)
__device__ float2 g_dtA[512 * NS];
__device__ float2 g_C2 [512 * NS];
__device__ float4 g_R64[512 * NS];

__device__ __forceinline__ void sincos_dr(float x, float* s, float* c) {
    // accurate sin/cos of an f32 value: double Cody-Waite reduction + fast sincos
    double pd = (double)x;
    double k  = rint(pd * 0.15915494309189535);      // x / (2*pi)
    float red = (float)__fma_rn(k, -6.283185307179586, pd);
    __sincosf(red, s, c);
}

__device__ __forceinline__ unsigned long long pack2(float lo, float hi) {
    unsigned long long r;
    asm("mov.b64 %0, {%1, %2};" : "=l"(r)
        : "r"(__float_as_uint(lo)), "r"(__float_as_uint(hi)));
    return r;
}

// acc += z; z = z * r  (complex, packed f32x2: lo=re, hi=im)
// rrp = (rr, rr)   rip = (-ri, ri)
__device__ __forceinline__ void cstep(unsigned long long& z, unsigned long long& acc,
                                      unsigned long long rrp, unsigned long long rip) {
    asm("{\n\t"
        ".reg .b32 zl, zh;\n\t"
        ".reg .b64 sw, u;\n\t"
        "add.rn.f32x2 %1, %1, %0;\n\t"
        "mov.b64 {zl, zh}, %0;\n\t"
        "mov.b64 sw, {zh, zl};\n\t"
        "mul.rn.f32x2 u, sw, %3;\n\t"
        "fma.rn.f32x2 %0, %0, %2, u;\n\t"
        "}\n"
        : "+l"(z), "+l"(acc)
        : "l"(rrp), "l"(rip));
}

// ---------------------------------------------------------------------------
__global__ void loong_pre(const float* __restrict__ C_real,
                          const float* __restrict__ log_dt,
                          const float* __restrict__ log_A_real,
                          const float* __restrict__ A_imag,
                          const float* __restrict__ omega_logit,
                          const float* __restrict__ eta_logit,
                          int H, int NST, int M) {
    const float OMIN = 1e-6f, OMAX = 100.0f, EMIN = 1e-6f, EMAX = 10.0f;
    int idx = blockIdx.x * blockDim.x + threadIdx.x;
    int total = H * M * NST;
    if (idx >= total) return;
    int h = idx / (M * NST);
    int j = idx - h * (M * NST);
    int m = j / NST;
    int n = j - m * NST;

    float dt    = expf(log_dt[h]);
    float omega = OMIN + (OMAX - OMIN) / (1.f + expf(-omega_logit[m]));
    float eta   = EMIN + (EMAX - EMIN) / (1.f + expf(-eta_logit[m]));
    float Are   = -expf(log_A_real[h * NST + n]);
    float Aim   = A_imag[h * NST + n];
    float Afr   = -omega + eta * Are;
    float Afi   = eta * Aim;
    float Cr    = eta * C_real[(h * NST + n) * 2 + 0];   // CH = 1
    float Ci    = eta * C_real[(h * NST + n) * 2 + 1];
    float dtAr  = Afr * dt;
    float dtAi  = Afi * dt;

    // (exp(dtA) - 1) / (A_frac + 1e-8)
    float er = expf(dtAr);
    float s1, c1; sincos_dr(dtAi, &s1, &c1);
    float nr = er * c1 - 1.f;
    float ni = er * s1;
    float dr  = Afr + 1e-8f, di = Afi;
    float inv = 1.f / (dr * dr + di * di);
    float qr  = (nr * dr + ni * di) * inv;
    float qi  = (ni * dr - nr * di) * inv;
    float Cdr = Cr * qr - Ci * qi;
    float Cdi = Cr * qi + Ci * qr;
    if (sqrtf(Afr * Afr + Afi * Afi) < 1e-6f) { Cdr = Cr * dt; Cdi = Ci * dt; }

    g_dtA[idx] = make_float2(dtAr, dtAi);
    g_C2 [idx] = make_float2(2.f * Cdr, 2.f * Cdi);

    // r64 = exp(64 * dtA)   (x64 exact in fp32)
    float e64 = expf(64.f * dtAr);
    float s64, c64; sincos_dr(64.f * dtAi, &s64, &c64);
    float rr = e64 * c64, ri = e64 * s64;
    g_R64[idx] = make_float4(rr, 0.f, -ri, ri);
}

// ---------------------------------------------------------------------------
__global__ __launch_bounds__(256) void loong_main(float* __restrict__ out, int L) {
    const int h   = blockIdx.x;
    const int tid = threadIdx.x;
    const int g   = tid >> 6;      // state group 0..3
    const int t   = tid & 63;      // l lane 0..63
    const int base = h * NS + g * GS;

    // --- seed 16 states into registers ---
    unsigned long long z[GS], rrp[GS], rip[GS];
    const float tf = (float)t;
#pragma unroll
    for (int i = 0; i < GS; i++) {
        float2 a = g_dtA[base + i];
        float2 c = g_C2 [base + i];
        float4 q = g_R64[base + i];
        float er = __expf(a.x * tf);
        float s, co; sincos_dr(a.y * tf, &s, &co);
        float zr = er * co, zi = er * s;
        z[i]   = pack2(c.x * zr - c.y * zi, c.x * zi + c.y * zr);
        rrp[i] = pack2(q.x, q.x);
        rip[i] = pack2(q.z, q.w);          // (-ri, ri)
    }

    __shared__ float sR[KCHUNK][4][64];    // 32 KB
    const int iters = (L + 63) >> 6;
    const long long ob = (long long)h * L;

    for (int k0 = 0; k0 < iters; k0 += KCHUNK) {
        const int kend = (iters - k0 < KCHUNK) ? (iters - k0) : KCHUNK;
#pragma unroll 1
        for (int k = 0; k < kend; k++) {
            unsigned long long acc = 0ull;
#pragma unroll
            for (int i = 0; i < GS; i++) cstep(z[i], acc, rrp[i], rip[i]);
            sR[k][g][t] = __uint_as_float((unsigned)acc);   // real part
        }
        __syncthreads();
        // coalesced epilogue: sum the 4 group partials
        const int lbeg = k0 << 6;
        const int lend = (k0 + kend) << 6;
        for (int l = lbeg + tid; l < lend && l < L; l += 256) {
            int kk = (l >> 6) - k0, tt = l & 63;
            out[ob + l] = sR[kk][0][tt] + sR[kk][1][tt]
                        + sR[kk][2][tt] + sR[kk][3][tt];
        }
        __syncthreads();
    }
}

// ---------------------------------------------------------------------------
extern "C" void kernel_launch(void* const* d_in, const int* in_sizes, int n_in,
                              void* d_out, int out_size) {
    const float* C_real      = (const float*)d_in[0];
    const float* log_dt      = (const float*)d_in[1];
    const float* log_A_real  = (const float*)d_in[2];
    const float* A_imag      = (const float*)d_in[3];
    const float* omega_logit = (const float*)d_in[4];
    const float* eta_logit   = (const float*)d_in[5];

    int H   = in_sizes[1];               // 512
    int NST = in_sizes[2] / H;           // 32
    int M   = in_sizes[4];               // 2
    int L   = out_size / H;              // 2048 (CH = 1)

    int total = H * M * NST;
    loong_pre<<<(total + 127) / 128, 128>>>(C_real, log_dt, log_A_real, A_imag,
                                            omega_logit, eta_logit, H, NST, M);
    loong_main<<<H, 256>>>((float*)d_out, L);
}